// round 6
// baseline (speedup 1.0000x reference)
#include <cuda_runtime.h>
#include <cuda_bf16.h>
#include <cstdint>
#include <cstddef>

// ============================================================================
// out[16384,2048] = (x @ W^T) * (1/sqrt(2048)) + 0.1*b
// tcgen05 path (sm_103a pass): double-bf16 split (hi+lo) -> 3 accumulating
// bf16 MMAs; cluster-2 with multicast B; 2-stage cp.async.bulk pipeline with
// deferred commit-wait; TMEM accumulators; fused scale+bias epilogue.
// Fallback path (plain sm_103 pass): SIMT fp32 GEMM, same launch config.
// ============================================================================

#if defined(__CUDA_ARCH_FEAT_SM103_ALL) || defined(__CUDA_ARCH_FEAT_SM100_ALL) \
 || defined(__CUDA_ARCH_FEAT_SM101_ALL) \
 || (defined(__CUDA_ARCH_SPECIFIC__) && (__CUDA_ARCH_SPECIFIC__ >= 1000)) \
 || (defined(__CUDA_ARCH_FAMILY_SPECIFIC__) && (__CUDA_ARCH_FAMILY_SPECIFIC__ >= 1000))
#define HAS_TCGEN05 1
#else
#define HAS_TCGEN05 0
#endif

#define N_ROWS 16384
#define D_IN   2048
#define D_OUT  2048

#define TM 128
#define TN 256
#define KC 64                       // K elements per stage (128B bf16 rows, SW128)
#define NKT (D_IN / KC)             // 32 K-iterations
#define KSTEPS (KC / 16)            // 4 MMA k-steps per iteration

#define A_TILE_BYTES (2 * TM * KC * 2)   // hi+lo A tile: 32768 B
#define B_TILE_BYTES (2 * TN * KC * 2)   // hi+lo B tile: 65536 B
#define STAGE_BYTES  (A_TILE_BYTES + B_TILE_BYTES)  // 98304 B

#define SMEM_TMEMPTR 0
// barrier block base; offsets: full{0,1}=+0,+8  cb{0,1}=+16,+24  final=+32  empty{0,1}=+40,+48
#define SMEM_BAR     64
#define SMEM_STAGE0  1024
#define SMEM_TOTAL   (SMEM_STAGE0 + 2 * STAGE_BYTES)  // 197632 B

#define TMEM_COLS 256

// idesc kind::f16: F32 acc (bit4), BF16 a (bit7), BF16 b (bit10), N=128, M=128
#define MMA_IDESC ((1u << 4) | (1u << 7) | (1u << 10) | ((128u / 8u) << 17) | ((128u / 16u) << 24))

// ---------------- scratch (device globals: allocation-free) ----------------
__device__ __align__(128) unsigned char g_X[(size_t)(N_ROWS / TM) * NKT * A_TILE_BYTES]; // 128 MB
__device__ __align__(128) unsigned char g_W[(size_t)(D_OUT / TN) * NKT * B_TILE_BYTES];  // 16 MB

// ---------------- portable helpers (sm_90+) ----------------
__device__ __forceinline__ uint32_t smem_u32(const void* p) {
    uint32_t a;
    asm("{ .reg .u64 t; cvta.to.shared.u64 t, %1; cvt.u32.u64 %0, t; }" : "=r"(a) : "l"(p));
    return a;
}

__device__ __forceinline__ void mbar_init(uint32_t mbar, uint32_t count) {
    asm volatile("mbarrier.init.shared.b64 [%0], %1;" :: "r"(mbar), "r"(count) : "memory");
}

__device__ __forceinline__ void mbar_expect_tx(uint32_t mbar, uint32_t bytes) {
    asm volatile("mbarrier.arrive.expect_tx.shared.b64 _, [%0], %1;"
                 :: "r"(mbar), "r"(bytes) : "memory");
}

__device__ __forceinline__ void mbar_wait(uint32_t mbar, uint32_t parity) {
    asm volatile(
        "{\n\t"
        ".reg .pred P;\n\t"
        "WAIT_%=:\n\t"
        "mbarrier.try_wait.parity.acquire.cta.shared::cta.b64 P, [%0], %1, 0x989680;\n\t"
        "@!P bra WAIT_%=;\n\t"
        "}\n"
        :: "r"(mbar), "r"(parity) : "memory");
}

// Wait on a barrier that receives cluster-scope arrivals (peer CTA releases).
__device__ __forceinline__ void mbar_wait_cluster(uint32_t mbar, uint32_t parity) {
    asm volatile(
        "{\n\t"
        ".reg .pred P;\n\t"
        "WAITC_%=:\n\t"
        "mbarrier.try_wait.parity.acquire.cluster.shared::cta.b64 P, [%0], %1, 0x989680;\n\t"
        "@!P bra WAITC_%=;\n\t"
        "}\n"
        :: "r"(mbar), "r"(parity) : "memory");
}

__device__ __forceinline__ void bulk_g2s(uint32_t dst_smem, const void* src_gmem,
                                         uint32_t bytes, uint32_t mbar) {
    asm volatile(
        "cp.async.bulk.shared::cluster.global.mbarrier::complete_tx::bytes [%0], [%1], %2, [%3];"
        :: "r"(dst_smem), "l"(src_gmem), "r"(bytes), "r"(mbar) : "memory");
}

// Arrive on rank-0's mbarrier at the same SMEM offset (cross-CTA release).
__device__ __forceinline__ void remote_arrive_rank0(uint32_t local_mbar) {
    asm volatile(
        "{\n\t"
        ".reg .b32 r;\n\t"
        "mapa.shared::cluster.u32 r, %0, 0;\n\t"
        "mbarrier.arrive.release.cluster.shared::cluster.b64 _, [r];\n\t"
        "}"
        :: "r"(local_mbar) : "memory");
}

// 64-bit SMEM matrix descriptor, SW128, Blackwell (LBO=1, SBO=64)
__device__ __forceinline__ uint64_t make_desc(uint32_t smem_addr) {
    const uint64_t BASE = (uint64_t(2) << 61)
                        | (uint64_t(1) << 46)
                        | (uint64_t(64) << 32)
                        | (uint64_t(1) << 16);
    return BASE | ((uint64_t)(smem_addr >> 4) & 0x3FFF);
}

#if HAS_TCGEN05
// ---------------- 'a'-pass only wrappers ----------------
__device__ __forceinline__ void bulk_g2s_mc(uint32_t dst_smem, const void* src_gmem,
                                            uint32_t bytes, uint32_t mbar, uint16_t mask) {
    asm volatile(
        "cp.async.bulk.shared::cluster.global.mbarrier::complete_tx::bytes.multicast::cluster"
        " [%0], [%1], %2, [%3], %4;"
        :: "r"(dst_smem), "l"(src_gmem), "r"(bytes), "r"(mbar), "h"(mask) : "memory");
}

__device__ __forceinline__ void mma_f16_ss(uint32_t d_tmem, uint64_t a_desc, uint64_t b_desc,
                                           uint32_t en) {
    asm volatile(
        "{\n\t"
        ".reg .pred p;\n\t"
        "setp.ne.u32 p, %5, 0;\n\t"
        "tcgen05.mma.cta_group::1.kind::f16 [%0], %1, %2, %3, {%4, %4, %4, %4}, p;\n\t"
        "}"
        :: "r"(d_tmem), "l"(a_desc), "l"(b_desc), "r"(MMA_IDESC), "r"(0u), "r"(en)
        : "memory");
}

__device__ __forceinline__ void tcommit(uint32_t mbar) {
    asm volatile("tcgen05.commit.cta_group::1.mbarrier::arrive::one.shared::cluster.b64 [%0];"
                 :: "r"(mbar) : "memory");
}

#define TLD_32X32B_X32(r, tmem_addr) \
    asm volatile( \
        "tcgen05.ld.sync.aligned.32x32b.x32.b32 " \
        "{%0, %1, %2, %3, %4, %5, %6, %7, " \
        " %8, %9, %10, %11, %12, %13, %14, %15, " \
        " %16, %17, %18, %19, %20, %21, %22, %23, " \
        " %24, %25, %26, %27, %28, %29, %30, %31}, [%32];" \
        : "=r"((r)[0]),  "=r"((r)[1]),  "=r"((r)[2]),  "=r"((r)[3]), \
          "=r"((r)[4]),  "=r"((r)[5]),  "=r"((r)[6]),  "=r"((r)[7]), \
          "=r"((r)[8]),  "=r"((r)[9]),  "=r"((r)[10]), "=r"((r)[11]), \
          "=r"((r)[12]), "=r"((r)[13]), "=r"((r)[14]), "=r"((r)[15]), \
          "=r"((r)[16]), "=r"((r)[17]), "=r"((r)[18]), "=r"((r)[19]), \
          "=r"((r)[20]), "=r"((r)[21]), "=r"((r)[22]), "=r"((r)[23]), \
          "=r"((r)[24]), "=r"((r)[25]), "=r"((r)[26]), "=r"((r)[27]), \
          "=r"((r)[28]), "=r"((r)[29]), "=r"((r)[30]), "=r"((r)[31]) \
        : "r"(tmem_addr))
#endif  // HAS_TCGEN05

// ============================================================================
// Conversion: fp32 -> per-(row_tile, k_tile) [hi | lo] bf16 tiles, SW128
// swizzled so the GEMM bulk-copies straight into SMEM for MMA descriptors.
// ============================================================================
template <int TILE_R>
__global__ void __launch_bounds__(256) convert_kernel(const float* __restrict__ src) {
    unsigned char* dstBase = (TILE_R == 128) ? g_X : g_W;
    const int tk = blockIdx.x;
    const int tr = blockIdx.y;
    const size_t tileBytes = (size_t)TILE_R * KC * 2;
    unsigned char* hi = dstBase + (size_t)(tr * NKT + tk) * 2 * tileBytes;
    unsigned char* lo = hi + tileBytes;
    const int pairs = TILE_R * (KC / 2);
    for (int i = threadIdx.x; i < pairs; i += blockDim.x) {
        const int r = i >> 5;
        const int p = i & 31;
        const float2 v = *(const float2*)(src + (size_t)(tr * TILE_R + r) * D_IN + tk * KC + p * 2);
        const __nv_bfloat16 h0 = __float2bfloat16(v.x);
        const __nv_bfloat16 h1 = __float2bfloat16(v.y);
        const __nv_bfloat16 l0 = __float2bfloat16(v.x - __bfloat162float(h0));
        const __nv_bfloat16 l1 = __float2bfloat16(v.y - __bfloat162float(h1));
        const uint32_t off = (uint32_t)r * 128u + (uint32_t)p * 4u;
        const uint32_t sw = off ^ ((off >> 3) & 0x70);
        const uint32_t hp = ((uint32_t)__bfloat16_as_ushort(h1) << 16) | __bfloat16_as_ushort(h0);
        const uint32_t lp = ((uint32_t)__bfloat16_as_ushort(l1) << 16) | __bfloat16_as_ushort(l0);
        *(uint32_t*)(hi + sw) = hp;
        *(uint32_t*)(lo + sw) = lp;
    }
}

// ============================================================================
// GEMM. grid (D_OUT/TN, N_ROWS/TM), block 128, cluster (1,2,1):
// pair = same tn (shared B tile, multicast), adjacent tm.
// ============================================================================
__global__ __launch_bounds__(128, 1) __cluster_dims__(1, 2, 1)
void gemm_kernel(const float* __restrict__ x,
                 const float* __restrict__ w,
                 const float* __restrict__ bias,
                 float* __restrict__ out) {
#if HAS_TCGEN05
    (void)x; (void)w;
    extern __shared__ __align__(1024) unsigned char smem[];
    const uint32_t sb = smem_u32(smem);
    const int tid = threadIdx.x;
    const int wid = tid >> 5, lid = tid & 31;
    const int tn = blockIdx.x;
    const int tm = blockIdx.y;

    uint32_t rank;
    asm("mov.u32 %0, %%cluster_ctarank;" : "=r"(rank));

    const uint32_t FULL0  = sb + SMEM_BAR + 0;
    const uint32_t CB0    = sb + SMEM_BAR + 16;
    const uint32_t FINAL  = sb + SMEM_BAR + 32;
    const uint32_t EMPTY0 = sb + SMEM_BAR + 40;

    if (tid == 0) {
        mbar_init(FULL0, 1);  mbar_init(FULL0 + 8, 1);
        mbar_init(CB0, 1);    mbar_init(CB0 + 8, 1);
        mbar_init(FINAL, 1);
        mbar_init(EMPTY0, 2); mbar_init(EMPTY0 + 8, 2);   // self + peer release
        asm volatile("fence.proxy.async.shared::cta;" ::: "memory");
    }
    if (wid == 0) {
        asm volatile("tcgen05.alloc.cta_group::1.sync.aligned.shared::cta.b32 [%0], %1;"
                     :: "r"(sb + SMEM_TMEMPTR), "r"(TMEM_COLS) : "memory");
    }
    __syncthreads();
    uint32_t tmem;
    asm volatile("ld.shared.b32 %0, [%1];" : "=r"(tmem) : "r"(sb + SMEM_TMEMPTR));
    if (wid == 0)
        asm volatile("tcgen05.relinquish_alloc_permit.cta_group::1.sync.aligned;");

    // barriers must be visible cluster-wide before any multicast targets them
    asm volatile("barrier.cluster.arrive.aligned;" ::: "memory");
    asm volatile("barrier.cluster.wait.aligned;" ::: "memory");

    if (tid == 0) {
        const unsigned char* aSrc = g_X + (size_t)tm * NKT * A_TILE_BYTES;
        const unsigned char* bSrc = g_W + (size_t)tn * NKT * B_TILE_BYTES;

        // ---- prologue: fill both stages (A per-CTA, B multicast by rank 0) ----
        #pragma unroll
        for (int s = 0; s < 2; s++) {
            const uint32_t st = sb + SMEM_STAGE0 + s * STAGE_BYTES;
            mbar_expect_tx(FULL0 + s * 8, STAGE_BYTES);
            bulk_g2s(st, aSrc + (size_t)s * A_TILE_BYTES, A_TILE_BYTES, FULL0 + s * 8);
        }
        if (rank == 0) {
            #pragma unroll
            for (int s = 0; s < 2; s++) {
                const uint32_t st = sb + SMEM_STAGE0 + s * STAGE_BYTES;
                bulk_g2s_mc(st + A_TILE_BYTES, bSrc + (size_t)s * B_TILE_BYTES,
                            B_TILE_BYTES, FULL0 + s * 8, (uint16_t)0x3);
            }
        }

        int fullPh[2] = {0, 0}, cbPh[2] = {0, 0}, emptyPh[2] = {0, 0};
        int pend = -1, pendTile = 0;

        for (int kt = 0; kt < NKT; kt++) {
            const int s = kt & 1;
            mbar_wait(FULL0 + s * 8, fullPh[s]); fullPh[s] ^= 1;

            const uint32_t st = sb + SMEM_STAGE0 + s * STAGE_BYTES;
            const uint64_t dAhi = make_desc(st);
            const uint64_t dAlo = make_desc(st + A_TILE_BYTES / 2);
            const uint64_t dBhi = make_desc(st + A_TILE_BYTES);
            const uint64_t dBlo = make_desc(st + A_TILE_BYTES + B_TILE_BYTES / 2);
            const uint64_t NH = 1024;  // +128 B-rows = 16384 B / 16

            #pragma unroll
            for (int ks = 0; ks < KSTEPS; ks++) {
                const uint64_t ko = (uint64_t)(ks * 2);
                const uint32_t acc = (kt | ks) ? 1u : 0u;
                mma_f16_ss(tmem,       dAhi + ko, dBhi + ko,      acc);
                mma_f16_ss(tmem + 128, dAhi + ko, dBhi + NH + ko, acc);
                mma_f16_ss(tmem,       dAhi + ko, dBlo + ko,      1u);
                mma_f16_ss(tmem + 128, dAhi + ko, dBlo + NH + ko, 1u);
                mma_f16_ss(tmem,       dAlo + ko, dBhi + ko,      1u);
                mma_f16_ss(tmem + 128, dAlo + ko, dBhi + NH + ko, 1u);
            }
            if (kt + 2 < NKT) tcommit(CB0 + s * 8);  // trips when MMAs <= kt retire

            // ---- deferred reload of the stage consumed LAST iteration ----
            if (pend >= 0) {
                const int ps = pend;
                const uint32_t pst = sb + SMEM_STAGE0 + ps * STAGE_BYTES;
                mbar_wait(CB0 + ps * 8, cbPh[ps]); cbPh[ps] ^= 1;    // MMAs(kt-1) done
                mbar_expect_tx(FULL0 + ps * 8, STAGE_BYTES);
                bulk_g2s(pst, aSrc + (size_t)pendTile * A_TILE_BYTES,
                         A_TILE_BYTES, FULL0 + ps * 8);
                remote_arrive_rank0(EMPTY0 + ps * 8);                 // release to B-issuer
                if (rank == 0) {
                    mbar_wait_cluster(EMPTY0 + ps * 8, emptyPh[ps]); emptyPh[ps] ^= 1;
                    bulk_g2s_mc(pst + A_TILE_BYTES,
                                bSrc + (size_t)pendTile * B_TILE_BYTES,
                                B_TILE_BYTES, FULL0 + ps * 8, (uint16_t)0x3);
                }
            }
            if (kt + 2 < NKT) { pend = s; pendTile = kt + 2; }
            else pend = -1;
        }
        tcommit(FINAL);  // all MMAs done
    }

    mbar_wait(FINAL, 0);
    asm volatile("tcgen05.fence::after_thread_sync;" ::: "memory");

    // ---- epilogue: TMEM -> XOR-swizzled SMEM -> coalesced GMEM ----
    const int r = wid * 32 + lid;
    uint32_t* epi = (uint32_t*)(smem + SMEM_STAGE0);   // 128 KB, stages dead
    #pragma unroll
    for (int cb = 0; cb < TN; cb += 32) {
        uint32_t regs[32];
        TLD_32X32B_X32(regs, tmem + cb);
        asm volatile("tcgen05.wait::ld.sync.aligned;" ::: "memory");
        #pragma unroll
        for (int j = 0; j < 32; j++) {
            const int c = cb + j;
            epi[r * TN + (c ^ (r & 31))] = regs[j];
        }
    }
    asm volatile("tcgen05.fence::before_thread_sync;" ::: "memory");
    __syncthreads();

    const float scale = 0.022097086912079608f;  // 1/sqrt(2048)
    float* outRow = out + (size_t)tm * TM * D_OUT + (size_t)tn * TN;
    const float* bch = bias + tn * TN;
    #pragma unroll 4
    for (int it = 0; it < (TM * TN) / 128; it++) {
        const int i = it * 128 + tid;
        const int rr = i >> 8;
        const int c = i & 255;
        const float v = __uint_as_float(epi[rr * TN + (c ^ (rr & 31))]);
        outRow[(size_t)rr * D_OUT + c] = v * scale + 0.1f * __ldg(bch + c);
    }

    __syncthreads();
    if (wid == 0)
        asm volatile("tcgen05.dealloc.cta_group::1.sync.aligned.b32 %0, %1;"
                     :: "r"(tmem), "r"(TMEM_COLS));

    // no CTA exits while peer multicasts could be in flight
    asm volatile("barrier.cluster.arrive.aligned;" ::: "memory");
    asm volatile("barrier.cluster.wait.aligned;" ::: "memory");

#else  // ======================= SIMT fp32 fallback =========================
    extern __shared__ __align__(16) float fsm[];
    float* ws = fsm;                 // 32 cols x 128 k  (16 KB)
    float* xs = fsm + 32 * 128;      // 128 rows x (128 k, pad to 132)  (66 KB)
    const int tid = threadIdx.x;
    const int tn = blockIdx.x, tm = blockIdx.y;
    const int row = tm * TM + tid;
    const float scale = 0.022097086912079608f;

    for (int nc = 0; nc < TN / 32; nc++) {
        const int cb = tn * TN + nc * 32;
        float acc[32];
        #pragma unroll
        for (int c = 0; c < 32; c++) acc[c] = 0.0f;

        for (int kb = 0; kb < D_IN; kb += 128) {
            __syncthreads();
            for (int i = tid; i < 32 * 128; i += 128)
                ws[i] = w[(size_t)(cb + (i >> 7)) * D_IN + kb + (i & 127)];
            for (int i = tid; i < 128 * 128; i += 128)
                xs[(i >> 7) * 132 + (i & 127)] = x[(size_t)(tm * TM + (i >> 7)) * D_IN + kb + (i & 127)];
            __syncthreads();

            #pragma unroll 2
            for (int k4 = 0; k4 < 32; k4++) {
                const float4 xv = *(const float4*)&xs[tid * 132 + k4 * 4];
                #pragma unroll
                for (int c = 0; c < 32; c++) {
                    const float4 wv = *(const float4*)&ws[(c << 7) + (k4 << 2)];
                    acc[c] += xv.x * wv.x + xv.y * wv.y + xv.z * wv.z + xv.w * wv.w;
                }
            }
        }
        #pragma unroll
        for (int c = 0; c < 32; c++)
            out[(size_t)row * D_OUT + cb + c] = acc[c] * scale + 0.1f * bias[cb + c];
    }
#endif
}

// ============================================================================
extern "C" void kernel_launch(void* const* d_in, const int* in_sizes, int n_in,
                              void* d_out, int out_size) {
    const float* x = (const float*)d_in[0];
    const float* w = (const float*)d_in[1];
    const float* b = (const float*)d_in[2];
    float* out = (float*)d_out;

    cudaFuncSetAttribute(gemm_kernel, cudaFuncAttributeMaxDynamicSharedMemorySize, SMEM_TOTAL);

    convert_kernel<128><<<dim3(NKT, N_ROWS / TM), 256>>>(x);   // x -> g_X (hi/lo, swizzled)
    convert_kernel<256><<<dim3(NKT, D_OUT / TN), 256>>>(w);    // W -> g_W
    gemm_kernel<<<dim3(D_OUT / TN, N_ROWS / TM), 128, SMEM_TOTAL>>>(x, w, b, out);
}

// round 8
// speedup vs baseline: 1.6628x; 1.6628x over previous
#include <cuda_runtime.h>
#include <cuda_bf16.h>
#include <cstdint>
#include <cstddef>

// ============================================================================
// out[16384,2048] = (x @ W^T) * (1/sqrt(2048)) + 0.1*b
// tcgen05 path (sm_103a): split x = hi + lo (bf16). Three passes, one loop:
//   it  0..31 : bf16  hi_x * hi_w              (KC=64 per chunk)
//   it 32..47 : e4m3 (hi_x*2^-4) * (lo_w*2^4)  (KC=128 per chunk) = hi_x*lo_w
//   it 48..63 : e4m3 (lo_x*2^4) * (hi_w*2^-4)  = lo_x*hi_w
// All stages uniform 64 KB; 256x256 tile/CTA, 4 TMEM quadrants (512 cols),
// 3-stage cp.async.bulk pipeline with commit-gated deferred reload (R6-
// validated plumbing). lo_x*lo_w (~2^-18) dropped.
// Fallback path (plain sm_103 pass): SIMT fp32 GEMM, same launch config.
// ============================================================================

#if defined(__CUDA_ARCH_FEAT_SM103_ALL) || defined(__CUDA_ARCH_FEAT_SM100_ALL) \
 || defined(__CUDA_ARCH_FEAT_SM101_ALL) \
 || (defined(__CUDA_ARCH_SPECIFIC__) && (__CUDA_ARCH_SPECIFIC__ >= 1000)) \
 || (defined(__CUDA_ARCH_FAMILY_SPECIFIC__) && (__CUDA_ARCH_FAMILY_SPECIFIC__ >= 1000))
#define HAS_TCGEN05 1
#else
#define HAS_TCGEN05 0
#endif

#define N_ROWS 16384
#define D_IN   2048
#define D_OUT  2048

#define TMSUB 128
#define TM    256
#define TN    256
#define NITER 64                    // 32 bf16 + 16 fp8 + 16 fp8
#define NSTAGE 3

// Tile units: one A sub-chunk tile = 16 KB (bf16 128x64 OR e4m3 128x128);
// one B chunk tile = 32 KB (bf16 256x64 OR e4m3 256x128). Both 128 B/row SW128.
#define A_UNIT 16384
#define B_UNIT 32768
#define STAGE_BYTES (2 * A_UNIT + B_UNIT)   // 65536

#define SMEM_TMEMPTR 0
#define SMEM_BAR     64              // full{0,1,2}=+0,8,16  cb{0,1,2}=+24,32,40  final=+48
#define SMEM_STAGE0  1024
#define SMEM_TOTAL   (SMEM_STAGE0 + NSTAGE * STAGE_BYTES)  // 197632 B

#define TMEM_COLS 512

// idesc fields (verified against f16 0x8080490 and mxf8 encodings):
// [4:6) c_format (F32=1), [7:10) a_format, [10:13) b_format,
// [17:23) N>>3, [24:29) M>>4.
#define MMA_IDESC_F16 ((1u << 4) | (1u << 7) | (1u << 10) | (16u << 17) | (8u << 24))
#define MMA_IDESC_F8  ((1u << 4) | (0u << 7) | (0u << 10) | (16u << 17) | (8u << 24))

// fp8 operand scales (cancel in the product): hi8 = e4m3(hi * 2^-4), lo8 = e4m3(lo * 2^4)
#define SHI 0.0625f
#define SLO 16.0f

// ---------------- scratch (device globals: allocation-free) ----------------
// Per row-tile layout, units of A_UNIT/B_UNIT "tiles":
//   tiles  0..31 : bf16 hi chunks (64 K-elems each)
//   tiles 32..47 : e4m3 hi8 chunks (128 K-elems each)
//   tiles 48..63 : e4m3 lo8 chunks
__device__ __align__(128) unsigned char g_X[(size_t)(N_ROWS / TMSUB) * 64 * A_UNIT]; // 128 MB
__device__ __align__(128) unsigned char g_W[(size_t)(D_OUT / TN)    * 64 * B_UNIT]; // 16 MB

// ---------------- portable helpers (sm_90+) ----------------
__device__ __forceinline__ uint32_t smem_u32(const void* p) {
    uint32_t a;
    asm("{ .reg .u64 t; cvta.to.shared.u64 t, %1; cvt.u32.u64 %0, t; }" : "=r"(a) : "l"(p));
    return a;
}

__device__ __forceinline__ void mbar_init(uint32_t mbar, uint32_t count) {
    asm volatile("mbarrier.init.shared.b64 [%0], %1;" :: "r"(mbar), "r"(count) : "memory");
}

__device__ __forceinline__ void mbar_expect_tx(uint32_t mbar, uint32_t bytes) {
    asm volatile("mbarrier.arrive.expect_tx.shared.b64 _, [%0], %1;"
                 :: "r"(mbar), "r"(bytes) : "memory");
}

__device__ __forceinline__ void mbar_wait(uint32_t mbar, uint32_t parity) {
    asm volatile(
        "{\n\t"
        ".reg .pred P;\n\t"
        "WAIT_%=:\n\t"
        "mbarrier.try_wait.parity.acquire.cta.shared::cta.b64 P, [%0], %1, 0x989680;\n\t"
        "@!P bra WAIT_%=;\n\t"
        "}\n"
        :: "r"(mbar), "r"(parity) : "memory");
}

__device__ __forceinline__ void bulk_g2s(uint32_t dst_smem, const void* src_gmem,
                                         uint32_t bytes, uint32_t mbar) {
    asm volatile(
        "cp.async.bulk.shared::cluster.global.mbarrier::complete_tx::bytes [%0], [%1], %2, [%3];"
        :: "r"(dst_smem), "l"(src_gmem), "r"(bytes), "r"(mbar) : "memory");
}

// 64-bit SMEM matrix descriptor, SW128, Blackwell (LBO=1, SBO=64)
__device__ __forceinline__ uint64_t make_desc(uint32_t smem_addr) {
    const uint64_t BASE = (uint64_t(2) << 61)
                        | (uint64_t(1) << 46)
                        | (uint64_t(64) << 32)
                        | (uint64_t(1) << 16);
    return BASE | ((uint64_t)(smem_addr >> 4) & 0x3FFF);
}

// two floats -> packed e4m3x2 (r[7:0]=cvt(lo_operand), r[15:8]=cvt(hi_operand))
__device__ __forceinline__ uint16_t f2_e4m3x2(float hi, float lo) {
    uint16_t r;
    asm("cvt.rn.satfinite.e4m3x2.f32 %0, %1, %2;" : "=h"(r) : "f"(hi), "f"(lo));
    return r;
}

#if HAS_TCGEN05
// ---------------- 'a'-pass only wrappers ----------------
__device__ __forceinline__ void mma_f16_ss(uint32_t d_tmem, uint64_t a_desc, uint64_t b_desc,
                                           uint32_t en) {
    asm volatile(
        "{\n\t"
        ".reg .pred p;\n\t"
        "setp.ne.u32 p, %5, 0;\n\t"
        "tcgen05.mma.cta_group::1.kind::f16 [%0], %1, %2, %3, {%4, %4, %4, %4}, p;\n\t"
        "}"
        :: "r"(d_tmem), "l"(a_desc), "l"(b_desc), "r"(MMA_IDESC_F16), "r"(0u), "r"(en)
        : "memory");
}

__device__ __forceinline__ void mma_f8_ss(uint32_t d_tmem, uint64_t a_desc, uint64_t b_desc,
                                          uint32_t en) {
    asm volatile(
        "{\n\t"
        ".reg .pred p;\n\t"
        "setp.ne.u32 p, %5, 0;\n\t"
        "tcgen05.mma.cta_group::1.kind::f8f6f4 [%0], %1, %2, %3, {%4, %4, %4, %4}, p;\n\t"
        "}"
        :: "r"(d_tmem), "l"(a_desc), "l"(b_desc), "r"(MMA_IDESC_F8), "r"(0u), "r"(en)
        : "memory");
}

__device__ __forceinline__ void tcommit(uint32_t mbar) {
    asm volatile("tcgen05.commit.cta_group::1.mbarrier::arrive::one.shared::cluster.b64 [%0];"
                 :: "r"(mbar) : "memory");
}

#define TLD_32X32B_X32(r, tmem_addr) \
    asm volatile( \
        "tcgen05.ld.sync.aligned.32x32b.x32.b32 " \
        "{%0, %1, %2, %3, %4, %5, %6, %7, " \
        " %8, %9, %10, %11, %12, %13, %14, %15, " \
        " %16, %17, %18, %19, %20, %21, %22, %23, " \
        " %24, %25, %26, %27, %28, %29, %30, %31}, [%32];" \
        : "=r"((r)[0]),  "=r"((r)[1]),  "=r"((r)[2]),  "=r"((r)[3]), \
          "=r"((r)[4]),  "=r"((r)[5]),  "=r"((r)[6]),  "=r"((r)[7]), \
          "=r"((r)[8]),  "=r"((r)[9]),  "=r"((r)[10]), "=r"((r)[11]), \
          "=r"((r)[12]), "=r"((r)[13]), "=r"((r)[14]), "=r"((r)[15]), \
          "=r"((r)[16]), "=r"((r)[17]), "=r"((r)[18]), "=r"((r)[19]), \
          "=r"((r)[20]), "=r"((r)[21]), "=r"((r)[22]), "=r"((r)[23]), \
          "=r"((r)[24]), "=r"((r)[25]), "=r"((r)[26]), "=r"((r)[27]), \
          "=r"((r)[28]), "=r"((r)[29]), "=r"((r)[30]), "=r"((r)[31]) \
        : "r"(tmem_addr))
#endif  // HAS_TCGEN05

// ============================================================================
// Conversion: fp32 [rows, 2048] -> per row-tile:
//   2 bf16-hi tiles per 128-K superchunk (SW128 swizzled, 64 K-elems each)
//   1 hi8 tile (e4m3(hi*2^-4), 128 K-elems) + 1 lo8 tile (e4m3(lo*2^4))
// grid (16 superchunks, n_row_tiles), block 256.
// ============================================================================
template <int TILE_R>
__global__ void __launch_bounds__(256) convert_kernel(const float* __restrict__ src) {
    unsigned char* dstBase = (TILE_R == TMSUB) ? g_X : g_W;
    const int tk = blockIdx.x;   // superchunk (128 K-elems)
    const int tr = blockIdx.y;
    const size_t tile = (size_t)TILE_R * 128;   // bytes per tile (same for bf16/fp8)
    unsigned char* base = dstBase + (size_t)tr * (64 * tile);
    unsigned char* hiB16a = base + (size_t)(2 * tk)     * tile;
    unsigned char* hiB16b = base + (size_t)(2 * tk + 1) * tile;
    unsigned char* hi8    = base + (size_t)(32 + tk)    * tile;
    unsigned char* lo8    = base + (size_t)(48 + tk)    * tile;

    const int quads = TILE_R * 32;   // 4 K-elems per quad
    for (int t = threadIdx.x; t < quads; t += 256) {
        const int r = t >> 5;
        const int q = t & 31;
        const float4 v = *(const float4*)(src + (size_t)(tr * TILE_R + r) * D_IN + tk * 128 + q * 4);

        const __nv_bfloat16 h0 = __float2bfloat16(v.x);
        const __nv_bfloat16 h1 = __float2bfloat16(v.y);
        const __nv_bfloat16 h2 = __float2bfloat16(v.z);
        const __nv_bfloat16 h3 = __float2bfloat16(v.w);
        const float f0 = __bfloat162float(h0), f1 = __bfloat162float(h1);
        const float f2 = __bfloat162float(h2), f3 = __bfloat162float(h3);
        const float l0 = v.x - f0, l1 = v.y - f1, l2 = v.z - f2, l3 = v.w - f3;

        // bf16 hi store: 8 bytes into chunk (q<16 ? a : b), col (q*4)&63
        const uint32_t offB = (uint32_t)r * 128u + (uint32_t)((q * 4) & 63) * 2u;
        const uint32_t swB = offB ^ ((offB >> 3) & 0x70);
        unsigned char* bt = (q < 16) ? hiB16a : hiB16b;
        uint2 hp;
        hp.x = ((uint32_t)__bfloat16_as_ushort(h1) << 16) | __bfloat16_as_ushort(h0);
        hp.y = ((uint32_t)__bfloat16_as_ushort(h3) << 16) | __bfloat16_as_ushort(h2);
        *(uint2*)(bt + swB) = hp;

        // fp8 stores: 4 bytes each, byte offset r*128 + q*4
        const uint32_t off8 = (uint32_t)r * 128u + (uint32_t)q * 4u;
        const uint32_t sw8 = off8 ^ ((off8 >> 3) & 0x70);
        const uint32_t wHi = (uint32_t)f2_e4m3x2(f1 * SHI, f0 * SHI)
                           | ((uint32_t)f2_e4m3x2(f3 * SHI, f2 * SHI) << 16);
        const uint32_t wLo = (uint32_t)f2_e4m3x2(l1 * SLO, l0 * SLO)
                           | ((uint32_t)f2_e4m3x2(l3 * SLO, l2 * SLO) << 16);
        *(uint32_t*)(hi8 + sw8) = wHi;
        *(uint32_t*)(lo8 + sw8) = wLo;
    }
}

// iteration -> B tile unit (A unit is just `it`):
// it<32: bf16 hi_w (unit it); 32<=it<48: lo8_w (unit it+16); it>=48: hi8_w (unit it-16)
__device__ __forceinline__ int b_unit(int j) {
    return j < 32 ? j : (j < 48 ? j + 16 : j - 16);
}

// ============================================================================
// GEMM: grid (D_OUT/TN=8, N_ROWS/TM=64), block 128. 256x256 tile per CTA.
// ============================================================================
__global__ void __launch_bounds__(128, 1) gemm_kernel(const float* __restrict__ x,
                                                      const float* __restrict__ w,
                                                      const float* __restrict__ bias,
                                                      float* __restrict__ out) {
#if HAS_TCGEN05
    (void)x; (void)w;
    extern __shared__ __align__(1024) unsigned char smem[];
    const uint32_t sb = smem_u32(smem);
    const int tid = threadIdx.x;
    const int wid = tid >> 5, lid = tid & 31;
    const int tn = blockIdx.x;   // 0..7
    const int tm = blockIdx.y;   // 0..63

    const uint32_t FULL  = sb + SMEM_BAR + 0;
    const uint32_t CB    = sb + SMEM_BAR + 24;
    const uint32_t FINAL = sb + SMEM_BAR + 48;

    if (tid == 0) {
        #pragma unroll
        for (int i = 0; i < NSTAGE; i++) { mbar_init(FULL + i * 8, 1); mbar_init(CB + i * 8, 1); }
        mbar_init(FINAL, 1);
        asm volatile("fence.proxy.async.shared::cta;" ::: "memory");
    }
    if (wid == 0) {
        asm volatile("tcgen05.alloc.cta_group::1.sync.aligned.shared::cta.b32 [%0], %1;"
                     :: "r"(sb + SMEM_TMEMPTR), "r"(TMEM_COLS) : "memory");
    }
    __syncthreads();
    uint32_t tmem;
    asm volatile("ld.shared.b32 %0, [%1];" : "=r"(tmem) : "r"(sb + SMEM_TMEMPTR));
    if (wid == 0)
        asm volatile("tcgen05.relinquish_alloc_permit.cta_group::1.sync.aligned;");
    __syncthreads();

    if (tid == 0) {
        const unsigned char* a0Src = g_X + (size_t)(tm * 2 + 0) * 64 * A_UNIT;
        const unsigned char* a1Src = g_X + (size_t)(tm * 2 + 1) * 64 * A_UNIT;
        const unsigned char* bSrc  = g_W + (size_t)tn * 64 * B_UNIT;

        // prologue: stages 0,1,2 <- iters 0,1,2
        #pragma unroll
        for (int s = 0; s < NSTAGE; s++) {
            const uint32_t st = sb + SMEM_STAGE0 + s * STAGE_BYTES;
            mbar_expect_tx(FULL + s * 8, STAGE_BYTES);
            bulk_g2s(st,              a0Src + (size_t)s * A_UNIT, A_UNIT, FULL + s * 8);
            bulk_g2s(st + A_UNIT,     a1Src + (size_t)s * A_UNIT, A_UNIT, FULL + s * 8);
            bulk_g2s(st + 2 * A_UNIT, bSrc + (size_t)b_unit(s) * B_UNIT, B_UNIT, FULL + s * 8);
        }

        int fullPh[NSTAGE] = {0, 0, 0}, cbPh[NSTAGE] = {0, 0, 0};

        for (int it = 0; it < NITER; it++) {
            const int s = it % NSTAGE;
            mbar_wait(FULL + s * 8, fullPh[s]); fullPh[s] ^= 1;

            const uint32_t st = sb + SMEM_STAGE0 + s * STAGE_BYTES;
            const uint64_t dA0 = make_desc(st);
            const uint64_t dA1 = make_desc(st + A_UNIT);
            const uint64_t dB  = make_desc(st + 2 * A_UNIT);
            const uint64_t NH = 1024;  // +128 B-rows = 16384 B / 16

            if (it < 32) {
                #pragma unroll
                for (int ks = 0; ks < 4; ks++) {
                    const uint64_t ko = (uint64_t)(ks * 2);   // +32 B = 16 bf16 K-elems
                    const uint32_t acc = (it | ks) ? 1u : 0u;
                    mma_f16_ss(tmem +   0, dA0 + ko, dB + ko,      acc);
                    mma_f16_ss(tmem + 128, dA0 + ko, dB + NH + ko, acc);
                    mma_f16_ss(tmem + 256, dA1 + ko, dB + ko,      acc);
                    mma_f16_ss(tmem + 384, dA1 + ko, dB + NH + ko, acc);
                }
            } else {
                #pragma unroll
                for (int ks = 0; ks < 4; ks++) {
                    const uint64_t ko = (uint64_t)(ks * 2);   // +32 B = 32 e4m3 K-elems
                    mma_f8_ss(tmem +   0, dA0 + ko, dB + ko,      1u);
                    mma_f8_ss(tmem + 128, dA0 + ko, dB + NH + ko, 1u);
                    mma_f8_ss(tmem + 256, dA1 + ko, dB + ko,      1u);
                    mma_f8_ss(tmem + 384, dA1 + ko, dB + NH + ko, 1u);
                }
            }
            if (it + NSTAGE < NITER) tcommit(CB + s * 8);

            // deferred reload: iter j=it+2 into stage (it+2)%3 (consumed at it-1),
            // gated on that stage's commit (issued at it-1).
            if (it >= 1 && it + 2 < NITER) {
                const int ps = (it + 2) % NSTAGE;
                const int j = it + 2;
                mbar_wait(CB + ps * 8, cbPh[ps]); cbPh[ps] ^= 1;
                const uint32_t pst = sb + SMEM_STAGE0 + ps * STAGE_BYTES;
                mbar_expect_tx(FULL + ps * 8, STAGE_BYTES);
                bulk_g2s(pst,              a0Src + (size_t)j * A_UNIT, A_UNIT, FULL + ps * 8);
                bulk_g2s(pst + A_UNIT,     a1Src + (size_t)j * A_UNIT, A_UNIT, FULL + ps * 8);
                bulk_g2s(pst + 2 * A_UNIT, bSrc + (size_t)b_unit(j) * B_UNIT, B_UNIT, FULL + ps * 8);
            }
        }
        tcommit(FINAL);  // all MMAs done
    }

    mbar_wait(FINAL, 0);
    asm volatile("tcgen05.fence::after_thread_sync;" ::: "memory");

    // ---- epilogue: two 128-row halves, TMEM -> swizzled SMEM -> coalesced GMEM
    const int r = wid * 32 + lid;
    uint32_t* epi = (uint32_t*)(smem + SMEM_STAGE0);   // staging (stages dead)
    const float scale = 0.022097086912079608f;         // 1/sqrt(2048)
    const float* bch = bias + tn * TN;

    #pragma unroll
    for (int h = 0; h < 2; h++) {
        const uint32_t tbase = tmem + h * 256;
        #pragma unroll
        for (int cb = 0; cb < TN; cb += 32) {
            uint32_t regs[32];
            TLD_32X32B_X32(regs, tbase + cb);
            asm volatile("tcgen05.wait::ld.sync.aligned;" ::: "memory");
            #pragma unroll
            for (int j = 0; j < 32; j++) {
                const int c = cb + j;
                epi[r * TN + (c ^ (r & 31))] = regs[j];
            }
        }
        __syncthreads();

        float* outRow = out + (size_t)(tm * TM + h * TMSUB) * D_OUT + (size_t)tn * TN;
        #pragma unroll 4
        for (int itl = 0; itl < (TMSUB * TN) / 128; itl++) {
            const int i = itl * 128 + tid;
            const int rr = i >> 8;
            const int c = i & 255;
            const float v = __uint_as_float(epi[rr * TN + (c ^ (rr & 31))]);
            outRow[(size_t)rr * D_OUT + c] = v * scale + 0.1f * __ldg(bch + c);
        }
        __syncthreads();
    }

    if (wid == 0)
        asm volatile("tcgen05.dealloc.cta_group::1.sync.aligned.b32 %0, %1;"
                     :: "r"(tmem), "r"(TMEM_COLS));

#else  // ======================= SIMT fp32 fallback =========================
    extern __shared__ __align__(16) float fsm[];
    float* ws = fsm;                 // 32 cols x 128 k  (16 KB)
    float* xs = fsm + 32 * 128;      // 128 rows x 132   (66 KB)
    const int tid = threadIdx.x;
    const int tn = blockIdx.x, tm = blockIdx.y;
    const float scale = 0.022097086912079608f;

    for (int sub = 0; sub < 2; sub++) {
        const int rowBase = tm * TM + sub * TMSUB;
        const int row = rowBase + tid;
        for (int nc = 0; nc < TN / 32; nc++) {
            const int cb = tn * TN + nc * 32;
            float acc[32];
            #pragma unroll
            for (int c = 0; c < 32; c++) acc[c] = 0.0f;

            for (int kb = 0; kb < D_IN; kb += 128) {
                __syncthreads();
                for (int i = tid; i < 32 * 128; i += 128)
                    ws[i] = w[(size_t)(cb + (i >> 7)) * D_IN + kb + (i & 127)];
                for (int i = tid; i < 128 * 128; i += 128)
                    xs[(i >> 7) * 132 + (i & 127)] = x[(size_t)(rowBase + (i >> 7)) * D_IN + kb + (i & 127)];
                __syncthreads();

                #pragma unroll 2
                for (int k4 = 0; k4 < 32; k4++) {
                    const float4 xv = *(const float4*)&xs[tid * 132 + k4 * 4];
                    #pragma unroll
                    for (int c = 0; c < 32; c++) {
                        const float4 wv = *(const float4*)&ws[(c << 7) + (k4 << 2)];
                        acc[c] += xv.x * wv.x + xv.y * wv.y + xv.z * wv.z + xv.w * wv.w;
                    }
                }
            }
            #pragma unroll
            for (int c = 0; c < 32; c++)
                out[(size_t)row * D_OUT + cb + c] = acc[c] * scale + 0.1f * bias[cb + c];
        }
    }
#endif
}

// ============================================================================
extern "C" void kernel_launch(void* const* d_in, const int* in_sizes, int n_in,
                              void* d_out, int out_size) {
    const float* x = (const float*)d_in[0];
    const float* w = (const float*)d_in[1];
    const float* b = (const float*)d_in[2];
    float* out = (float*)d_out;

    cudaFuncSetAttribute(gemm_kernel, cudaFuncAttributeMaxDynamicSharedMemorySize, SMEM_TOTAL);

    convert_kernel<TMSUB><<<dim3(D_IN / 128, N_ROWS / TMSUB), 256>>>(x);  // x -> g_X
    convert_kernel<TN>   <<<dim3(D_IN / 128, D_OUT / TN),     256>>>(w);  // W -> g_W
    gemm_kernel<<<dim3(D_OUT / TN, N_ROWS / TM), 128, SMEM_TOTAL>>>(x, w, b, out);
}

// round 11
// speedup vs baseline: 2.2526x; 1.3547x over previous
#include <cuda_runtime.h>
#include <cuda_bf16.h>
#include <cstdint>
#include <cstddef>

// ============================================================================
// out[16384,2048] = (x @ W^T) * (1/sqrt(2048)) + 0.1*b
// tcgen05 path (sm_103a): x = hi + lo (bf16 split). One 64-iteration loop:
//   it  0..31 : bf16  hi_x * hi_w              (KC=64 per chunk)
//   it 32..47 : e4m3 (hi_x*2^-4) * (lo_w*2^4)  (KC=128)  = hi_x*lo_w
//   it 48..63 : e4m3 (lo_x*2^4) * (hi_w*2^-4)            = lo_x*hi_w
// R9 changes vs R8 (both slots ran ~2400cyc regardless of bytes/dispatches ->
// control-serialization limited):
//   * warp-specialized: tid0 = TMA producer, tid32 = MMA issuer (decoupled)
//   * N=256 single MMA per (kstep, subtile): 8 dispatches/iter instead of 16
// Fallback path (plain sm_103 pass): SIMT fp32 GEMM, same launch config.
// ============================================================================

#if defined(__CUDA_ARCH_FEAT_SM103_ALL) || defined(__CUDA_ARCH_FEAT_SM100_ALL) \
 || defined(__CUDA_ARCH_FEAT_SM101_ALL) \
 || (defined(__CUDA_ARCH_SPECIFIC__) && (__CUDA_ARCH_SPECIFIC__ >= 1000)) \
 || (defined(__CUDA_ARCH_FAMILY_SPECIFIC__) && (__CUDA_ARCH_FAMILY_SPECIFIC__ >= 1000))
#define HAS_TCGEN05 1
#else
#define HAS_TCGEN05 0
#endif

#define N_ROWS 16384
#define D_IN   2048
#define D_OUT  2048

#define TMSUB 128
#define TM    256
#define TN    256
#define NITER 64                    // 32 bf16 + 16 fp8 + 16 fp8
#define NSTAGE 3

// A sub-chunk tile = 16 KB (bf16 128x64 or e4m3 128x128); B chunk tile = 32 KB
// (bf16 256x64 or e4m3 256x128). All rows 128 B, SW128.
#define A_UNIT 16384
#define B_UNIT 32768
#define STAGE_BYTES (2 * A_UNIT + B_UNIT)   // 65536

#define SMEM_TMEMPTR 0
#define SMEM_BAR     64              // full{0,1,2}=+0,8,16  cb{0,1,2}=+24,32,40  final=+48
#define SMEM_STAGE0  1024
#define SMEM_TOTAL   (SMEM_STAGE0 + NSTAGE * STAGE_BYTES)  // 197632 B

#define TMEM_COLS 512

// idesc fields: [4:6) c=F32=1, [7:10) a_fmt, [10:13) b_fmt, [17:23) N>>3, [24:29) M>>4.
// N=256 per dispatch.
#define MMA_IDESC_F16 ((1u << 4) | (1u << 7) | (1u << 10) | (32u << 17) | (8u << 24))
#define MMA_IDESC_F8  ((1u << 4) | (0u << 7) | (0u << 10) | (32u << 17) | (8u << 24))

// fp8 operand scales (cancel in the product)
#define SHI 0.0625f
#define SLO 16.0f

// ---------------- scratch (device globals: allocation-free) ----------------
// Per row-tile, tile units: 0..31 bf16-hi chunks; 32..47 e4m3 hi8; 48..63 e4m3 lo8.
__device__ __align__(128) unsigned char g_X[(size_t)(N_ROWS / TMSUB) * 64 * A_UNIT]; // 128 MB
__device__ __align__(128) unsigned char g_W[(size_t)(D_OUT / TN)    * 64 * B_UNIT]; // 16 MB

// ---------------- portable helpers (sm_90+) ----------------
__device__ __forceinline__ uint32_t smem_u32(const void* p) {
    uint32_t a;
    asm("{ .reg .u64 t; cvta.to.shared.u64 t, %1; cvt.u32.u64 %0, t; }" : "=r"(a) : "l"(p));
    return a;
}

__device__ __forceinline__ void mbar_init(uint32_t mbar, uint32_t count) {
    asm volatile("mbarrier.init.shared.b64 [%0], %1;" :: "r"(mbar), "r"(count) : "memory");
}

__device__ __forceinline__ void mbar_expect_tx(uint32_t mbar, uint32_t bytes) {
    asm volatile("mbarrier.arrive.expect_tx.shared.b64 _, [%0], %1;"
                 :: "r"(mbar), "r"(bytes) : "memory");
}

__device__ __forceinline__ void mbar_wait(uint32_t mbar, uint32_t parity) {
    asm volatile(
        "{\n\t"
        ".reg .pred P;\n\t"
        "WAIT_%=:\n\t"
        "mbarrier.try_wait.parity.acquire.cta.shared::cta.b64 P, [%0], %1, 0x989680;\n\t"
        "@!P bra WAIT_%=;\n\t"
        "}\n"
        :: "r"(mbar), "r"(parity) : "memory");
}

__device__ __forceinline__ void bulk_g2s(uint32_t dst_smem, const void* src_gmem,
                                         uint32_t bytes, uint32_t mbar) {
    asm volatile(
        "cp.async.bulk.shared::cluster.global.mbarrier::complete_tx::bytes [%0], [%1], %2, [%3];"
        :: "r"(dst_smem), "l"(src_gmem), "r"(bytes), "r"(mbar) : "memory");
}

// 64-bit SMEM matrix descriptor, SW128, Blackwell (LBO=1, SBO=64)
__device__ __forceinline__ uint64_t make_desc(uint32_t smem_addr) {
    const uint64_t BASE = (uint64_t(2) << 61)
                        | (uint64_t(1) << 46)
                        | (uint64_t(64) << 32)
                        | (uint64_t(1) << 16);
    return BASE | ((uint64_t)(smem_addr >> 4) & 0x3FFF);
}

__device__ __forceinline__ uint16_t f2_e4m3x2(float hi, float lo) {
    uint16_t r;
    asm("cvt.rn.satfinite.e4m3x2.f32 %0, %1, %2;" : "=h"(r) : "f"(hi), "f"(lo));
    return r;
}

#if HAS_TCGEN05
// ---------------- 'a'-pass only wrappers ----------------
__device__ __forceinline__ void mma_f16_ss(uint32_t d_tmem, uint64_t a_desc, uint64_t b_desc,
                                           uint32_t en) {
    asm volatile(
        "{\n\t"
        ".reg .pred p;\n\t"
        "setp.ne.u32 p, %5, 0;\n\t"
        "tcgen05.mma.cta_group::1.kind::f16 [%0], %1, %2, %3, {%4, %4, %4, %4}, p;\n\t"
        "}"
        :: "r"(d_tmem), "l"(a_desc), "l"(b_desc), "r"(MMA_IDESC_F16), "r"(0u), "r"(en)
        : "memory");
}

__device__ __forceinline__ void mma_f8_ss(uint32_t d_tmem, uint64_t a_desc, uint64_t b_desc,
                                          uint32_t en) {
    asm volatile(
        "{\n\t"
        ".reg .pred p;\n\t"
        "setp.ne.u32 p, %5, 0;\n\t"
        "tcgen05.mma.cta_group::1.kind::f8f6f4 [%0], %1, %2, %3, {%4, %4, %4, %4}, p;\n\t"
        "}"
        :: "r"(d_tmem), "l"(a_desc), "l"(b_desc), "r"(MMA_IDESC_F8), "r"(0u), "r"(en)
        : "memory");
}

__device__ __forceinline__ void tcommit(uint32_t mbar) {
    asm volatile("tcgen05.commit.cta_group::1.mbarrier::arrive::one.shared::cluster.b64 [%0];"
                 :: "r"(mbar) : "memory");
}

#define TLD_32X32B_X32(r, tmem_addr) \
    asm volatile( \
        "tcgen05.ld.sync.aligned.32x32b.x32.b32 " \
        "{%0, %1, %2, %3, %4, %5, %6, %7, " \
        " %8, %9, %10, %11, %12, %13, %14, %15, " \
        " %16, %17, %18, %19, %20, %21, %22, %23, " \
        " %24, %25, %26, %27, %28, %29, %30, %31}, [%32];" \
        : "=r"((r)[0]),  "=r"((r)[1]),  "=r"((r)[2]),  "=r"((r)[3]), \
          "=r"((r)[4]),  "=r"((r)[5]),  "=r"((r)[6]),  "=r"((r)[7]), \
          "=r"((r)[8]),  "=r"((r)[9]),  "=r"((r)[10]), "=r"((r)[11]), \
          "=r"((r)[12]), "=r"((r)[13]), "=r"((r)[14]), "=r"((r)[15]), \
          "=r"((r)[16]), "=r"((r)[17]), "=r"((r)[18]), "=r"((r)[19]), \
          "=r"((r)[20]), "=r"((r)[21]), "=r"((r)[22]), "=r"((r)[23]), \
          "=r"((r)[24]), "=r"((r)[25]), "=r"((r)[26]), "=r"((r)[27]), \
          "=r"((r)[28]), "=r"((r)[29]), "=r"((r)[30]), "=r"((r)[31]) \
        : "r"(tmem_addr))
#endif  // HAS_TCGEN05

// ============================================================================
// Conversion (unchanged from R8, validated): fp32 -> bf16-hi tiles + e4m3
// hi8/lo8 tiles, SW128 swizzled.
// ============================================================================
template <int TILE_R>
__global__ void __launch_bounds__(256) convert_kernel(const float* __restrict__ src) {
    unsigned char* dstBase = (TILE_R == TMSUB) ? g_X : g_W;
    const int tk = blockIdx.x;   // superchunk (128 K-elems)
    const int tr = blockIdx.y;
    const size_t tile = (size_t)TILE_R * 128;
    unsigned char* base = dstBase + (size_t)tr * (64 * tile);
    unsigned char* hiB16a = base + (size_t)(2 * tk)     * tile;
    unsigned char* hiB16b = base + (size_t)(2 * tk + 1) * tile;
    unsigned char* hi8    = base + (size_t)(32 + tk)    * tile;
    unsigned char* lo8    = base + (size_t)(48 + tk)    * tile;

    const int quads = TILE_R * 32;
    for (int t = threadIdx.x; t < quads; t += 256) {
        const int r = t >> 5;
        const int q = t & 31;
        const float4 v = *(const float4*)(src + (size_t)(tr * TILE_R + r) * D_IN + tk * 128 + q * 4);

        const __nv_bfloat16 h0 = __float2bfloat16(v.x);
        const __nv_bfloat16 h1 = __float2bfloat16(v.y);
        const __nv_bfloat16 h2 = __float2bfloat16(v.z);
        const __nv_bfloat16 h3 = __float2bfloat16(v.w);
        const float f0 = __bfloat162float(h0), f1 = __bfloat162float(h1);
        const float f2 = __bfloat162float(h2), f3 = __bfloat162float(h3);
        const float l0 = v.x - f0, l1 = v.y - f1, l2 = v.z - f2, l3 = v.w - f3;

        const uint32_t offB = (uint32_t)r * 128u + (uint32_t)((q * 4) & 63) * 2u;
        const uint32_t swB = offB ^ ((offB >> 3) & 0x70);
        unsigned char* bt = (q < 16) ? hiB16a : hiB16b;
        uint2 hp;
        hp.x = ((uint32_t)__bfloat16_as_ushort(h1) << 16) | __bfloat16_as_ushort(h0);
        hp.y = ((uint32_t)__bfloat16_as_ushort(h3) << 16) | __bfloat16_as_ushort(h2);
        *(uint2*)(bt + swB) = hp;

        const uint32_t off8 = (uint32_t)r * 128u + (uint32_t)q * 4u;
        const uint32_t sw8 = off8 ^ ((off8 >> 3) & 0x70);
        const uint32_t wHi = (uint32_t)f2_e4m3x2(f1 * SHI, f0 * SHI)
                           | ((uint32_t)f2_e4m3x2(f3 * SHI, f2 * SHI) << 16);
        const uint32_t wLo = (uint32_t)f2_e4m3x2(l1 * SLO, l0 * SLO)
                           | ((uint32_t)f2_e4m3x2(l3 * SLO, l2 * SLO) << 16);
        *(uint32_t*)(hi8 + sw8) = wHi;
        *(uint32_t*)(lo8 + sw8) = wLo;
    }
}

// iteration -> B tile unit (A unit is just `it`)
__device__ __forceinline__ int b_unit(int j) {
    return j < 32 ? j : (j < 48 ? j + 16 : j - 16);
}

// ============================================================================
// GEMM: grid (8, 64), block 128. 256x256 tile/CTA. Warp-specialized control:
//   tid 0  : TMA producer (CB-gated ring refill)
//   tid 32 : MMA issuer (FULL-gated, commits CB per iter)
// ============================================================================
__global__ void __launch_bounds__(128, 1) gemm_kernel(const float* __restrict__ x,
                                                      const float* __restrict__ w,
                                                      const float* __restrict__ bias,
                                                      float* __restrict__ out) {
#if HAS_TCGEN05
    (void)x; (void)w;
    extern __shared__ __align__(1024) unsigned char smem[];
    const uint32_t sb = smem_u32(smem);
    const int tid = threadIdx.x;
    const int wid = tid >> 5, lid = tid & 31;
    const int tn = blockIdx.x;   // 0..7
    const int tm = blockIdx.y;   // 0..63

    const uint32_t FULL  = sb + SMEM_BAR + 0;
    const uint32_t CB    = sb + SMEM_BAR + 24;
    const uint32_t FINAL = sb + SMEM_BAR + 48;

    if (tid == 0) {
        #pragma unroll
        for (int i = 0; i < NSTAGE; i++) { mbar_init(FULL + i * 8, 1); mbar_init(CB + i * 8, 1); }
        mbar_init(FINAL, 1);
        asm volatile("fence.proxy.async.shared::cta;" ::: "memory");
    }
    if (wid == 0) {
        asm volatile("tcgen05.alloc.cta_group::1.sync.aligned.shared::cta.b32 [%0], %1;"
                     :: "r"(sb + SMEM_TMEMPTR), "r"(TMEM_COLS) : "memory");
    }
    __syncthreads();
    uint32_t tmem;
    asm volatile("ld.shared.b32 %0, [%1];" : "=r"(tmem) : "r"(sb + SMEM_TMEMPTR));
    if (wid == 0)
        asm volatile("tcgen05.relinquish_alloc_permit.cta_group::1.sync.aligned;");
    __syncthreads();

    if (tid == 0) {
        // ---------------- PRODUCER ----------------
        const unsigned char* a0Src = g_X + (size_t)(tm * 2 + 0) * 64 * A_UNIT;
        const unsigned char* a1Src = g_X + (size_t)(tm * 2 + 1) * 64 * A_UNIT;
        const unsigned char* bSrc  = g_W + (size_t)tn * 64 * B_UNIT;

        int cbPh[NSTAGE] = {0, 0, 0};
        for (int j = 0; j < NITER; j++) {
            const int s = j % NSTAGE;
            if (j >= NSTAGE) { mbar_wait(CB + s * 8, cbPh[s]); cbPh[s] ^= 1; }  // stage free
            const uint32_t st = sb + SMEM_STAGE0 + s * STAGE_BYTES;
            mbar_expect_tx(FULL + s * 8, STAGE_BYTES);
            bulk_g2s(st,              a0Src + (size_t)j * A_UNIT, A_UNIT, FULL + s * 8);
            bulk_g2s(st + A_UNIT,     a1Src + (size_t)j * A_UNIT, A_UNIT, FULL + s * 8);
            bulk_g2s(st + 2 * A_UNIT, bSrc + (size_t)b_unit(j) * B_UNIT, B_UNIT, FULL + s * 8);
        }
    } else if (tid == 32) {
        // ---------------- MMA ISSUER ----------------
        int fullPh[NSTAGE] = {0, 0, 0};
        for (int it = 0; it < NITER; it++) {
            const int s = it % NSTAGE;
            mbar_wait(FULL + s * 8, fullPh[s]); fullPh[s] ^= 1;

            const uint32_t st = sb + SMEM_STAGE0 + s * STAGE_BYTES;
            const uint64_t dA0 = make_desc(st);
            const uint64_t dA1 = make_desc(st + A_UNIT);
            const uint64_t dB  = make_desc(st + 2 * A_UNIT);

            if (it < 32) {
                #pragma unroll
                for (int ks = 0; ks < 4; ks++) {
                    const uint64_t ko = (uint64_t)(ks * 2);   // +32 B = 16 bf16 K-elems
                    const uint32_t acc = (it | ks) ? 1u : 0u;
                    mma_f16_ss(tmem +   0, dA0 + ko, dB + ko, acc);   // sub0, N=256
                    mma_f16_ss(tmem + 256, dA1 + ko, dB + ko, acc);   // sub1, N=256
                }
            } else {
                #pragma unroll
                for (int ks = 0; ks < 4; ks++) {
                    const uint64_t ko = (uint64_t)(ks * 2);   // +32 B = 32 e4m3 K-elems
                    mma_f8_ss(tmem +   0, dA0 + ko, dB + ko, 1u);
                    mma_f8_ss(tmem + 256, dA1 + ko, dB + ko, 1u);
                }
            }
            tcommit(CB + s * 8);   // releases stage s (trips when MMAs <= it retire)
        }
        tcommit(FINAL);
    }

    mbar_wait(FINAL, 0);
    asm volatile("tcgen05.fence::after_thread_sync;" ::: "memory");

    // ---- epilogue: two 128-row halves, TMEM -> swizzled SMEM -> coalesced GMEM
    const int r = wid * 32 + lid;
    uint32_t* epi = (uint32_t*)(smem + SMEM_STAGE0);
    const float scale = 0.022097086912079608f;  // 1/sqrt(2048)
    const float* bch = bias + tn * TN;

    #pragma unroll
    for (int h = 0; h < 2; h++) {
        const uint32_t tbase = tmem + h * 256;   // sub h occupies cols [h*256, h*256+256)
        #pragma unroll
        for (int cb = 0; cb < TN; cb += 32) {
            uint32_t regs[32];
            TLD_32X32B_X32(regs, tbase + cb);
            asm volatile("tcgen05.wait::ld.sync.aligned;" ::: "memory");
            #pragma unroll
            for (int j = 0; j < 32; j++) {
                const int c = cb + j;
                epi[r * TN + (c ^ (r & 31))] = regs[j];
            }
        }
        __syncthreads();

        float* outRow = out + (size_t)(tm * TM + h * TMSUB) * D_OUT + (size_t)tn * TN;
        #pragma unroll 4
        for (int itl = 0; itl < (TMSUB * TN) / 128; itl++) {
            const int i = itl * 128 + tid;
            const int rr = i >> 8;
            const int c = i & 255;
            const float v = __uint_as_float(epi[rr * TN + (c ^ (rr & 31))]);
            outRow[(size_t)rr * D_OUT + c] = v * scale + 0.1f * __ldg(bch + c);
        }
        __syncthreads();
    }

    if (wid == 0)
        asm volatile("tcgen05.dealloc.cta_group::1.sync.aligned.b32 %0, %1;"
                     :: "r"(tmem), "r"(TMEM_COLS));

#else  // ======================= SIMT fp32 fallback =========================
    extern __shared__ __align__(16) float fsm[];
    float* ws = fsm;                 // 32 cols x 128 k  (16 KB)
    float* xs = fsm + 32 * 128;      // 128 rows x 132   (66 KB)
    const int tid = threadIdx.x;
    const int tn = blockIdx.x, tm = blockIdx.y;
    const float scale = 0.022097086912079608f;

    for (int sub = 0; sub < 2; sub++) {
        const int rowBase = tm * TM + sub * TMSUB;
        const int row = rowBase + tid;
        for (int nc = 0; nc < TN / 32; nc++) {
            const int cb = tn * TN + nc * 32;
            float acc[32];
            #pragma unroll
            for (int c = 0; c < 32; c++) acc[c] = 0.0f;

            for (int kb = 0; kb < D_IN; kb += 128) {
                __syncthreads();
                for (int i = tid; i < 32 * 128; i += 128)
                    ws[i] = w[(size_t)(cb + (i >> 7)) * D_IN + kb + (i & 127)];
                for (int i = tid; i < 128 * 128; i += 128)
                    xs[(i >> 7) * 132 + (i & 127)] = x[(size_t)(rowBase + (i >> 7)) * D_IN + kb + (i & 127)];
                __syncthreads();

                #pragma unroll 2
                for (int k4 = 0; k4 < 32; k4++) {
                    const float4 xv = *(const float4*)&xs[tid * 132 + k4 * 4];
                    #pragma unroll
                    for (int c = 0; c < 32; c++) {
                        const float4 wv = *(const float4*)&ws[(c << 7) + (k4 << 2)];
                        acc[c] += xv.x * wv.x + xv.y * wv.y + xv.z * wv.z + xv.w * wv.w;
                    }
                }
            }
            #pragma unroll
            for (int c = 0; c < 32; c++)
                out[(size_t)row * D_OUT + cb + c] = acc[c] * scale + 0.1f * bias[cb + c];
        }
    }
#endif
}

// ============================================================================
extern "C" void kernel_launch(void* const* d_in, const int* in_sizes, int n_in,
                              void* d_out, int out_size) {
    const float* x = (const float*)d_in[0];
    const float* w = (const float*)d_in[1];
    const float* b = (const float*)d_in[2];
    float* out = (float*)d_out;

    cudaFuncSetAttribute(gemm_kernel, cudaFuncAttributeMaxDynamicSharedMemorySize, SMEM_TOTAL);

    convert_kernel<TMSUB><<<dim3(D_IN / 128, N_ROWS / TMSUB), 256>>>(x);  // x -> g_X
    convert_kernel<TN>   <<<dim3(D_IN / 128, D_OUT / TN),     256>>>(w);  // W -> g_W
    gemm_kernel<<<dim3(D_OUT / TN, N_ROWS / TM), 128, SMEM_TOTAL>>>(x, w, b, out);
}